// round 8
// baseline (speedup 1.0000x reference)
#include <cuda_runtime.h>
#include <stdint.h>

// diag(A) @ B : out[i][j] = A[i] * B[i][j]
// N = 8192 rows, M = 8192 cols, fp32. Pure HBM-streaming kernel.
//
// R7: best config (R4: one row per block, 512 thr x 4 float4, front-batched
// loads) with cache-policy split: loads stay .cs (evict-first, zero reuse),
// stores revert to default write-back so L2 can batch dirty lines into long
// DRAM write bursts (fewer read<->write bus turnarounds).

#define THREADS 512
#define UNROLL  4   // 512 * 4 * 4 floats = 8192 = M (one row per block)

__global__ void __launch_bounds__(THREADS) diag_scale_row_wb(
    const float* __restrict__ A,
    const float4* __restrict__ B4,
    float4* __restrict__ out4)
{
    const int row = blockIdx.x;                 // 8192 blocks = 8192 rows
    const float a = __ldg(&A[row]);

    const long long base = (long long)row * (THREADS * UNROLL) + threadIdx.x;

    // Front-batch all loads: 4 independent LDG.128 in flight per thread.
    float4 b[UNROLL];
#pragma unroll
    for (int k = 0; k < UNROLL; k++) {
        b[k] = __ldcs(&B4[base + (long long)k * THREADS]);
    }

#pragma unroll
    for (int k = 0; k < UNROLL; k++) {
        float4 o;
        o.x = a * b[k].x;
        o.y = a * b[k].y;
        o.z = a * b[k].z;
        o.w = a * b[k].w;
        out4[base + (long long)k * THREADS] = o;   // default write-back store
    }
}

extern "C" void kernel_launch(void* const* d_in, const int* in_sizes, int n_in,
                              void* d_out, int out_size)
{
    const float* A = (const float*)d_in[0];
    const float4* B4 = (const float4*)d_in[1];
    float4* out4 = (float4*)d_out;

    int n_rows = (int)((long long)out_size / 8192);  // 8192

    diag_scale_row_wb<<<n_rows, THREADS>>>(A, B4, out4);
}

// round 9
// speedup vs baseline: 1.0047x; 1.0047x over previous
#include <cuda_runtime.h>
#include <stdint.h>

// diag(A) @ B : out[i][j] = A[i] * B[i][j]
// N = 8192 rows, M = 8192 cols, fp32. Pure HBM-streaming kernel.
//
// R8: half-row per block (best wall-clock config), .cs loads, and
// write-through stores (st.global.wt.v4.f32) — stores bypass L2 dirty-line
// allocation entirely, removing writeback scheduling contention with the
// read stream at the LTS.

#define THREADS 256
#define UNROLL  4   // 256 * 4 * 4 floats = 4096 = M/2 (half row per block)

__device__ __forceinline__ void stg_wt_v4(float4* __restrict__ p, float4 v) {
    asm volatile(
        "st.global.wt.v4.f32 [%0], {%1,%2,%3,%4};"
        :: "l"(p), "f"(v.x), "f"(v.y), "f"(v.z), "f"(v.w)
        : "memory");
}

__global__ void __launch_bounds__(THREADS) diag_scale_halfrow_wt(
    const float* __restrict__ A,
    const float4* __restrict__ B4,
    float4* __restrict__ out4)
{
    const int row = blockIdx.x >> 1;               // 2 blocks per row
    const float a = __ldg(&A[row]);

    const long long base = (long long)blockIdx.x * (THREADS * UNROLL) + threadIdx.x;

    // Front-batch all loads: 4 independent LDG.128 in flight per thread.
    float4 b[UNROLL];
#pragma unroll
    for (int k = 0; k < UNROLL; k++) {
        b[k] = __ldcs(&B4[base + (long long)k * THREADS]);
    }

#pragma unroll
    for (int k = 0; k < UNROLL; k++) {
        float4 o;
        o.x = a * b[k].x;
        o.y = a * b[k].y;
        o.z = a * b[k].z;
        o.w = a * b[k].w;
        stg_wt_v4(&out4[base + (long long)k * THREADS], o);
    }
}

extern "C" void kernel_launch(void* const* d_in, const int* in_sizes, int n_in,
                              void* d_out, int out_size)
{
    const float* A = (const float*)d_in[0];
    const float4* B4 = (const float4*)d_in[1];
    float4* out4 = (float4*)d_out;

    int n_rows = (int)((long long)out_size / 8192);
    int blocks = n_rows * 2;                       // 16384

    diag_scale_halfrow_wt<<<blocks, THREADS>>>(A, B4, out4);
}

// round 10
// speedup vs baseline: 1.0098x; 1.0051x over previous
#include <cuda_runtime.h>
#include <stdint.h>

// diag(A) @ B : out[i][j] = A[i] * B[i][j]
// N = 8192 rows, M = 8192 cols, fp32. Pure HBM-streaming kernel.
//
// R9 (final config probe): one row per block, 512 thr x 4 float4 front-batched
// (best-measured structure, R4 = 73.5us kernel / DRAM 82.6%).
// Cache-policy: .cg loads (L2-only, normal replacement priority) + .cs stores
// (evict-first) — the last untested load/store policy combination.

#define THREADS 512
#define UNROLL  4   // 512 * 4 * 4 floats = 8192 = M (one row per block)

__global__ void __launch_bounds__(THREADS) diag_scale_row_cg(
    const float* __restrict__ A,
    const float4* __restrict__ B4,
    float4* __restrict__ out4)
{
    const int row = blockIdx.x;                 // 8192 blocks = 8192 rows
    const float a = __ldg(&A[row]);

    const long long base = (long long)row * (THREADS * UNROLL) + threadIdx.x;

    // Front-batch all loads: 4 independent LDG.128.CG in flight per thread.
    float4 b[UNROLL];
#pragma unroll
    for (int k = 0; k < UNROLL; k++) {
        b[k] = __ldcg(&B4[base + (long long)k * THREADS]);
    }

#pragma unroll
    for (int k = 0; k < UNROLL; k++) {
        float4 o;
        o.x = a * b[k].x;
        o.y = a * b[k].y;
        o.z = a * b[k].z;
        o.w = a * b[k].w;
        __stcs(&out4[base + (long long)k * THREADS], o);
    }
}

extern "C" void kernel_launch(void* const* d_in, const int* in_sizes, int n_in,
                              void* d_out, int out_size)
{
    const float* A = (const float*)d_in[0];
    const float4* B4 = (const float4*)d_in[1];
    float4* out4 = (float4*)d_out;

    int n_rows = (int)((long long)out_size / 8192);  // 8192

    diag_scale_row_cg<<<n_rows, THREADS>>>(A, B4, out4);
}

// round 11
// speedup vs baseline: 1.0113x; 1.0016x over previous
#include <cuda_runtime.h>
#include <stdint.h>

// diag(A) @ B : out[i][j] = A[i] * B[i][j]
// N = 8192 rows, M = 8192 cols, fp32. Pure HBM-streaming kernel.
//
// FINAL (R4 config, confirmed best over 9 measured variants):
//   - one block == one row: 512 threads x 4 float4 = 8192 floats = M
//   - loads front-batched (4 independent LDG.128 in flight, MLP_p1=4)
//   - .cs (evict-first) on BOTH loads and stores — measured best policy
//     (beats .wb stores, .wt stores, .cg loads, default loads)
//   - flat 8192-block grid; HW CTA scheduler overlaps waves
//   - 26 regs, no smem
// Measured: 73.5us kernel, DRAM 82.6% (6544 GB/s) — HBM read+write
// turnaround ceiling; all other pipes <6% (pure memory-bound roofline).

#define THREADS 512
#define UNROLL  4   // 512 * 4 * 4 floats = 8192 = M (one row per block)

__global__ void __launch_bounds__(THREADS) diag_scale_row512(
    const float* __restrict__ A,
    const float4* __restrict__ B4,
    float4* __restrict__ out4)
{
    const int row = blockIdx.x;                 // 8192 blocks = 8192 rows
    const float a = __ldg(&A[row]);

    const long long base = (long long)row * (THREADS * UNROLL) + threadIdx.x;

    // Front-batch all loads: 4 independent LDG.128 in flight per thread.
    float4 b[UNROLL];
#pragma unroll
    for (int k = 0; k < UNROLL; k++) {
        b[k] = __ldcs(&B4[base + (long long)k * THREADS]);
    }

#pragma unroll
    for (int k = 0; k < UNROLL; k++) {
        float4 o;
        o.x = a * b[k].x;
        o.y = a * b[k].y;
        o.z = a * b[k].z;
        o.w = a * b[k].w;
        __stcs(&out4[base + (long long)k * THREADS], o);
    }
}

extern "C" void kernel_launch(void* const* d_in, const int* in_sizes, int n_in,
                              void* d_out, int out_size)
{
    const float* A = (const float*)d_in[0];
    const float4* B4 = (const float4*)d_in[1];
    float4* out4 = (float4*)d_out;

    int n_rows = (int)((long long)out_size / 8192);  // 8192

    diag_scale_row512<<<n_rows, THREADS>>>(A, B4, out4);
}